// round 4
// baseline (speedup 1.0000x reference)
#include <cuda_runtime.h>
#include <cuda_bf16.h>
#include <cstdint>

// SoftEmbeddedDecisionRules: balanced binary hierarchy over C=1024 classes.
// One row per warp; per-lane-contiguous compute layout (MUFU-minimal).
// Global<->smem via 1D bulk-async copies (32KB per block, no tensor map).
// Smem is linear; bank conflicts avoided by rotated chunk order per lane.

#define BATCH_N 32768
#define NCLASS 1024
#define WARPS_PER_BLOCK 8
#define TILE_BYTES (WARPS_PER_BLOCK * NCLASS * 4)   // 32768 B per block

__device__ __forceinline__ float sigmoidf_fast(float x) {
    return __fdividef(1.0f, 1.0f + __expf(-x));
}

__global__ void __launch_bounds__(WARPS_PER_BLOCK * 32)
soft_tree_kernel(const float* __restrict__ in, float* __restrict__ out) {
    __shared__ alignas(128) float4 buf[TILE_BYTES / 16];   // 2048 float4 = 32KB
    __shared__ alignas(8) unsigned long long mbar;

    const int tid  = threadIdx.x;
    const int wib  = tid >> 5;
    const int lane = tid & 31;

    const uint32_t buf_s  = (uint32_t)__cvta_generic_to_shared(buf);
    const uint32_t mbar_s = (uint32_t)__cvta_generic_to_shared(&mbar);

    if (tid == 0) {
        asm volatile("mbarrier.init.shared.b64 [%0], %1;"
                     :: "r"(mbar_s), "r"(1) : "memory");
    }
    __syncthreads();

    if (tid == 0) {
        asm volatile("mbarrier.arrive.expect_tx.shared.b64 _, [%0], %1;"
                     :: "r"(mbar_s), "r"((uint32_t)TILE_BYTES) : "memory");
        const float* src = in + (size_t)blockIdx.x * (TILE_BYTES / 4);
        asm volatile(
            "cp.async.bulk.shared::cta.global.mbarrier::complete_tx::bytes "
            "[%0], [%1], %2, [%3];"
            :: "r"(buf_s), "l"(src), "r"((uint32_t)TILE_BYTES), "r"(mbar_s)
            : "memory");
    }

    // All threads wait for the bulk load (phase parity 0).
    {
        uint32_t done;
        asm volatile(
            "{\n\t.reg .pred p;\n\t"
            "mbarrier.try_wait.parity.shared.b64 p, [%1], %2;\n\t"
            "selp.b32 %0, 1, 0, p;\n\t}"
            : "=r"(done) : "r"(mbar_s), "r"(0) : "memory");
        while (!done) {
            asm volatile(
                "{\n\t.reg .pred p;\n\t"
                "mbarrier.try_wait.parity.shared.b64 p, [%1], %2;\n\t"
                "selp.b32 %0, 1, 0, p;\n\t}"
                : "=r"(done) : "r"(mbar_s), "r"(0) : "memory");
        }
    }

    // ---- phase A: read this lane's 32 contiguous classes (rotated order,
    //      conflict-free) and compute s2 sums + leaf sigmoids eagerly ----
    const int segbase = (wib * 32 + lane) * 8;   // first float4 chunk of lane's 128B seg
    float s2[16], a1[16];
#pragma unroll
    for (int t = 0; t < 8; t++) {
        int i = (t + lane) & 7;                  // rotation kills bank conflicts
        float4 q = buf[segbase + i];
        s2[2 * i + 0] = q.x + q.y;
        a1[2 * i + 0] = sigmoidf_fast(q.x - q.y);
        s2[2 * i + 1] = q.z + q.w;
        a1[2 * i + 1] = sigmoidf_fast(q.z - q.w);
    }

    // ---- upsweep with eager sigmoids ----
    float s4[8], a2[8];
#pragma unroll
    for (int i = 0; i < 8; i++) {
        s4[i] = s2[2 * i] + s2[2 * i + 1];
        a2[i] = sigmoidf_fast((s2[2 * i] - s2[2 * i + 1]) * 0.5f);
    }
    float s8[4], a4[4];
#pragma unroll
    for (int i = 0; i < 4; i++) {
        s8[i] = s4[2 * i] + s4[2 * i + 1];
        a4[i] = sigmoidf_fast((s4[2 * i] - s4[2 * i + 1]) * 0.25f);
    }
    float s16[2], a8[2];
#pragma unroll
    for (int i = 0; i < 2; i++) {
        s16[i] = s8[2 * i] + s8[2 * i + 1];
        a8[i] = sigmoidf_fast((s8[2 * i] - s8[2 * i + 1]) * 0.125f);
    }
    float S   = s16[0] + s16[1];
    float a16 = sigmoidf_fast((s16[0] - s16[1]) * 0.0625f);

    // ---- cross-lane levels: seg = 32, 64, 128, 256, 512 ----
    float F = 1.0f;
    {
        float o;
        o = __shfl_xor_sync(0xffffffffu, S, 1);
        F *= sigmoidf_fast((S - o) * (1.0f / 32.0f));  S += o;
        o = __shfl_xor_sync(0xffffffffu, S, 2);
        F *= sigmoidf_fast((S - o) * (1.0f / 64.0f));  S += o;
        o = __shfl_xor_sync(0xffffffffu, S, 4);
        F *= sigmoidf_fast((S - o) * (1.0f / 128.0f)); S += o;
        o = __shfl_xor_sync(0xffffffffu, S, 8);
        F *= sigmoidf_fast((S - o) * (1.0f / 256.0f)); S += o;
        o = __shfl_xor_sync(0xffffffffu, S, 16);
        F *= sigmoidf_fast((S - o) * (1.0f / 512.0f));
    }

    // ---- downsweep: multiply sigmoid factors top-down ----
    float p16[2];
    p16[0] = F * a16;
    p16[1] = F - p16[0];

    float p8[4];
#pragma unroll
    for (int i = 0; i < 2; i++) {
        p8[2 * i]     = p16[i] * a8[i];
        p8[2 * i + 1] = p16[i] - p8[2 * i];
    }
    float p4[8];
#pragma unroll
    for (int i = 0; i < 4; i++) {
        p4[2 * i]     = p8[i] * a4[i];
        p4[2 * i + 1] = p8[i] - p4[2 * i];
    }
    float p2[16];
#pragma unroll
    for (int i = 0; i < 8; i++) {
        p2[2 * i]     = p4[i] * a2[i];
        p2[2 * i + 1] = p4[i] - p2[2 * i];
    }

    // ---- leaves -> smem in place (own segments only; rotated, conflict-free) ----
#pragma unroll
    for (int t = 0; t < 8; t++) {
        int i = (t + lane) & 7;
        float4 w;
        w.x = p2[2 * i] * a1[2 * i];
        w.y = p2[2 * i] - w.x;
        w.z = p2[2 * i + 1] * a1[2 * i + 1];
        w.w = p2[2 * i + 1] - w.z;
        buf[segbase + i] = w;
    }

    __syncthreads();

    // ---- bulk store smem -> global ----
    if (tid == 0) {
        asm volatile("fence.proxy.async.shared::cta;" ::: "memory");
        float* dst = out + (size_t)blockIdx.x * (TILE_BYTES / 4);
        asm volatile(
            "cp.async.bulk.global.shared::cta.bulk_group [%0], [%1], %2;"
            :: "l"(dst), "r"(buf_s), "r"((uint32_t)TILE_BYTES) : "memory");
        asm volatile("cp.async.bulk.commit_group;" ::: "memory");
        asm volatile("cp.async.bulk.wait_group 0;" ::: "memory");
    }
}

extern "C" void kernel_launch(void* const* d_in, const int* in_sizes, int n_in,
                              void* d_out, int out_size) {
    (void)in_sizes; (void)n_in; (void)out_size;
    const float* in = (const float*)d_in[0];
    float* out = (float*)d_out;
    soft_tree_kernel<<<BATCH_N / WARPS_PER_BLOCK, WARPS_PER_BLOCK * 32>>>(in, out);
}